// round 6
// baseline (speedup 1.0000x reference)
#include <cuda_runtime.h>
#include <float.h>

#define NN   100000
#define IND  128
#define HIDD 256
#define NG   256

// ---------------- static device scratch (allocation-free rule) ----------------
__device__ float g_m[NN * IND];        // relu(x @ W_pool + b_pool)
__device__ float g_neigh[NN * IND];    // segment_max over in-edges
__device__ float g_h1[NN * HIDD];
__device__ float g_h2[NN * HIDD];
__device__ float g_h3[NN * HIDD];
__device__ float g_final[NG * HIDD];   // 1/zsum per (graph, feature)
__device__ int   g_start[NG + 1];      // node range per graph (graph_id sorted)

// ---------------- small utility kernels ----------------
__global__ void zero_neigh_kernel(int n4) {
    int i = blockIdx.x * blockDim.x + threadIdx.x;
    if (i < n4) reinterpret_cast<float4*>(g_neigh)[i] = make_float4(0.f, 0.f, 0.f, 0.f);
}

__global__ void init_start_kernel(int g1) {
    int i = blockIdx.x * blockDim.x + threadIdx.x;
    if (i < g1) g_start[i] = 0x7f7f7f7f;
}

__global__ void mark_starts_kernel(const int* __restrict__ gid, int n) {
    int i = blockIdx.x * blockDim.x + threadIdx.x;
    if (i < n) atomicMin(&g_start[gid[i]], i);
}

__global__ void fix_starts_kernel(int n_nodes, int n_graphs) {
    if (threadIdx.x == 0 && blockIdx.x == 0) {
        g_start[n_graphs] = n_nodes;
        for (int g = n_graphs - 1; g >= 0; --g)
            if (g_start[g] > g_start[g + 1]) g_start[g] = g_start[g + 1];
    }
}

// ---------------- fused (dual-A) GEMM + bias + relu ----------------
// C[M,N] = relu(A1[M,K1] @ B1[K1,N] + A2[M,K2] @ B2[K2,N] + bias)
// 128x128 block tile, BK=8, 256 threads, 8x8 per-thread microtile,
// register double-buffered global->smem staging.
template<int K1, int K2, int N>
__global__ __launch_bounds__(256, 2)
void gemm_bias_relu(const float* __restrict__ A1, const float* __restrict__ A2,
                    const float* __restrict__ B1, const float* __restrict__ B2,
                    const float* __restrict__ bias, float* __restrict__ C, int M)
{
    constexpr int KT = K1 + K2;
    constexpr int T  = KT / 8;

    __shared__ float As[8][132];   // transposed A tile, padded (conflict-free)
    __shared__ float Bs[8][128];

    const int tid     = threadIdx.x;
    const int rowbase = blockIdx.x * 128;
    const int colbase = blockIdx.y * 128;

    const int a_row  = tid >> 1;          // 0..127
    const int a_k0   = (tid & 1) * 4;     // 0 or 4
    const int a_grow = rowbase + a_row;
    const int b_krow = tid >> 5;          // 0..7
    const int b_q    = (tid & 31) * 4;    // 0..124

    const int tx = tid & 15;
    const int ty = tid >> 4;

    float acc[8][8];
#pragma unroll
    for (int i = 0; i < 8; ++i)
#pragma unroll
        for (int j = 0; j < 8; ++j) acc[i][j] = 0.f;

    float4 pa, pb;

    auto fetchA = [&](int t) {
        int kk = t * 8 + a_k0;
        if (a_grow >= M) { pa = make_float4(0.f, 0.f, 0.f, 0.f); return; }
        const float* p;
        if constexpr (K2 == 0) {
            p = A1 + a_grow * K1 + kk;
        } else {
            p = (kk < K1) ? (A1 + a_grow * K1 + kk)
                          : (A2 + a_grow * K2 + (kk - K1));
        }
        pa = *reinterpret_cast<const float4*>(p);
    };
    auto fetchB = [&](int t) {
        int kg = t * 8 + b_krow;
        const float* p;
        if constexpr (K2 == 0) {
            p = B1 + kg * N + colbase + b_q;
        } else {
            p = (kg < K1) ? (B1 + kg * N + colbase + b_q)
                          : (B2 + (kg - K1) * N + colbase + b_q);
        }
        pb = *reinterpret_cast<const float4*>(p);
    };

    fetchA(0);
    fetchB(0);

#pragma unroll 1
    for (int t = 0; t < T; ++t) {
        As[a_k0 + 0][a_row] = pa.x;
        As[a_k0 + 1][a_row] = pa.y;
        As[a_k0 + 2][a_row] = pa.z;
        As[a_k0 + 3][a_row] = pa.w;
        *reinterpret_cast<float4*>(&Bs[b_krow][b_q]) = pb;
        __syncthreads();

        if (t + 1 < T) { fetchA(t + 1); fetchB(t + 1); }

#pragma unroll
        for (int k = 0; k < 8; ++k) {
            float4 a0 = *reinterpret_cast<const float4*>(&As[k][ty * 8]);
            float4 a1 = *reinterpret_cast<const float4*>(&As[k][ty * 8 + 4]);
            float4 b0 = *reinterpret_cast<const float4*>(&Bs[k][tx * 8]);
            float4 b1 = *reinterpret_cast<const float4*>(&Bs[k][tx * 8 + 4]);
            float av[8] = {a0.x, a0.y, a0.z, a0.w, a1.x, a1.y, a1.z, a1.w};
            float bv[8] = {b0.x, b0.y, b0.z, b0.w, b1.x, b1.y, b1.z, b1.w};
#pragma unroll
            for (int i = 0; i < 8; ++i)
#pragma unroll
                for (int j = 0; j < 8; ++j)
                    acc[i][j] = fmaf(av[i], bv[j], acc[i][j]);
        }
        __syncthreads();
    }

    float bia[8];
#pragma unroll
    for (int j = 0; j < 8; ++j) bia[j] = bias[colbase + tx * 8 + j];

#pragma unroll
    for (int i = 0; i < 8; ++i) {
        int r = rowbase + ty * 8 + i;
        if (r < M) {
            float4 o0, o1;
            o0.x = fmaxf(acc[i][0] + bia[0], 0.f);
            o0.y = fmaxf(acc[i][1] + bia[1], 0.f);
            o0.z = fmaxf(acc[i][2] + bia[2], 0.f);
            o0.w = fmaxf(acc[i][3] + bia[3], 0.f);
            o1.x = fmaxf(acc[i][4] + bia[4], 0.f);
            o1.y = fmaxf(acc[i][5] + bia[5], 0.f);
            o1.z = fmaxf(acc[i][6] + bia[6], 0.f);
            o1.w = fmaxf(acc[i][7] + bia[7], 0.f);
            *reinterpret_cast<float4*>(&C[r * N + colbase + tx * 8])     = o0;
            *reinterpret_cast<float4*>(&C[r * N + colbase + tx * 8 + 4]) = o1;
        }
    }
}

// ---------------- edge segment_max (relu output >= 0 -> int atomicMax trick) ----
// warp per edge, lane handles 4 features; pre-read current max, atomic only
// on record-breaking values (monotone, race-safe).
__global__ void edge_max_kernel(const int* __restrict__ src, const int* __restrict__ dst,
                                int n_edges)
{
    int gt = blockIdx.x * blockDim.x + threadIdx.x;
    int e  = gt >> 5;
    if (e >= n_edges) return;
    int c = (gt & 31) * 4;
    int s = __ldg(&src[e]);
    int d = __ldg(&dst[e]);
    float4 v   = *reinterpret_cast<const float4*>(&g_m[s * IND + c]);
    float* nrow = &g_neigh[d * IND + c];
    float4 cur = *reinterpret_cast<const float4*>(nrow);
    int*   ni  = reinterpret_cast<int*>(nrow);
    if (v.x > cur.x) atomicMax(ni + 0, __float_as_int(v.x));
    if (v.y > cur.y) atomicMax(ni + 1, __float_as_int(v.y));
    if (v.z > cur.z) atomicMax(ni + 2, __float_as_int(v.z));
    if (v.w > cur.w) atomicMax(ni + 3, __float_as_int(v.w));
}

// ---------------- per-graph online softmax denominator ----------------
// final[g,f] = max_nodes(exp(h-gmax)/zsum) = 1/zsum (exp is monotone, gmax = max h)
// One block per graph, one thread per feature, 4 independent online chains for MLP.
__global__ void softmax_final_kernel()
{
    int g = blockIdx.x;
    int f = threadIdx.x;
    int s = g_start[g], e = g_start[g + 1];
    const float* __restrict__ h = g_h3;

    float mx0 = -FLT_MAX, mx1 = -FLT_MAX, mx2 = -FLT_MAX, mx3 = -FLT_MAX;
    float s0 = 0.f, s1 = 0.f, s2 = 0.f, s3 = 0.f;

    int i = s;
    for (; i + 4 <= e; i += 4) {
        float v0 = h[(i + 0) * HIDD + f];
        float v1 = h[(i + 1) * HIDD + f];
        float v2 = h[(i + 2) * HIDD + f];
        float v3 = h[(i + 3) * HIDD + f];
        if (v0 > mx0) { s0 *= __expf(mx0 - v0); mx0 = v0; }
        s0 += __expf(v0 - mx0);
        if (v1 > mx1) { s1 *= __expf(mx1 - v1); mx1 = v1; }
        s1 += __expf(v1 - mx1);
        if (v2 > mx2) { s2 *= __expf(mx2 - v2); mx2 = v2; }
        s2 += __expf(v2 - mx2);
        if (v3 > mx3) { s3 *= __expf(mx3 - v3); mx3 = v3; }
        s3 += __expf(v3 - mx3);
    }
    for (; i < e; ++i) {
        float v = h[i * HIDD + f];
        if (v > mx0) { s0 *= __expf(mx0 - v); mx0 = v; }
        s0 += __expf(v - mx0);
    }

    float Mx = fmaxf(fmaxf(mx0, mx1), fmaxf(mx2, mx3));
    float S  = s0 * __expf(mx0 - Mx) + s1 * __expf(mx1 - Mx)
             + s2 * __expf(mx2 - Mx) + s3 * __expf(mx3 - Mx);
    g_final[g * HIDD + f] = (e > s) ? (1.0f / S) : 0.f;
}

// ---------------- tiny readout: out = final @ Wr + br ----------------
__global__ void readout_kernel(const float* __restrict__ Wr, const float* __restrict__ br,
                               float* __restrict__ out, int ngr)
{
    int t = blockIdx.x * blockDim.x + threadIdx.x;
    if (t < ngr * 2) {
        int g = t >> 1, o = t & 1;
        float acc = br[o];
        const float* fr = &g_final[g * HIDD];
#pragma unroll 8
        for (int f = 0; f < HIDD; ++f) acc = fmaf(fr[f], Wr[f * 2 + o], acc);
        out[t] = acc;
    }
}

// ---------------- launch ----------------
extern "C" void kernel_launch(void* const* d_in, const int* in_sizes, int n_in,
                              void* d_out, int out_size)
{
    const float* x       = (const float*)d_in[0];
    const float* W_pool  = (const float*)d_in[1];
    const float* b_pool  = (const float*)d_in[2];
    const float* W_self  = (const float*)d_in[3];
    const float* W_neigh = (const float*)d_in[4];
    const float* b_sage  = (const float*)d_in[5];
    const float* W1      = (const float*)d_in[6];
    const float* b1      = (const float*)d_in[7];
    const float* W2      = (const float*)d_in[8];
    const float* b2      = (const float*)d_in[9];
    const float* Wr      = (const float*)d_in[10];
    const float* br      = (const float*)d_in[11];
    const int*   src     = (const int*)d_in[12];
    const int*   dst     = (const int*)d_in[13];
    const int*   gid     = (const int*)d_in[14];
    float*       out     = (float*)d_out;

    const int M = in_sizes[0] / IND;   // 100000
    const int E = in_sizes[12];        // 1600000
    const int G = out_size / 2;        // 256

    void *pm, *pn, *ph1, *ph2, *ph3;
    cudaGetSymbolAddress(&pm,  g_m);
    cudaGetSymbolAddress(&pn,  g_neigh);
    cudaGetSymbolAddress(&ph1, g_h1);
    cudaGetSymbolAddress(&ph2, g_h2);
    cudaGetSymbolAddress(&ph3, g_h3);

    // stage 0: inits + graph ranges (independent of GEMMs)
    const int n4 = (M * IND) / 4;
    zero_neigh_kernel<<<(n4 + 255) / 256, 256>>>(n4);
    init_start_kernel<<<1, 512>>>(G + 1);
    mark_starts_kernel<<<(M + 255) / 256, 256>>>(gid, M);
    fix_starts_kernel<<<1, 32>>>(M, G);

    const int MB = (M + 127) / 128;

    // stage 1: m = relu(x @ W_pool + b_pool)
    gemm_bias_relu<128, 0, 128><<<dim3(MB, 1), 256>>>(
        x, nullptr, W_pool, nullptr, b_pool, (float*)pm, M);

    // stage 2: neigh = segment_max(m[src], dst)
    long ethreads = (long)E * 32;
    edge_max_kernel<<<(unsigned)((ethreads + 255) / 256), 256>>>(src, dst, E);

    // stage 3: h1 = relu(x @ W_self + neigh @ W_neigh + b_sage)   (fused K=256)
    gemm_bias_relu<128, 128, 256><<<dim3(MB, 2), 256>>>(
        x, (const float*)pn, W_self, W_neigh, b_sage, (float*)ph1, M);

    // stage 4/5: MLP
    gemm_bias_relu<256, 0, 256><<<dim3(MB, 2), 256>>>(
        (const float*)ph1, nullptr, W1, nullptr, b1, (float*)ph2, M);
    gemm_bias_relu<256, 0, 256><<<dim3(MB, 2), 256>>>(
        (const float*)ph2, nullptr, W2, nullptr, b2, (float*)ph3, M);

    // stage 6: per-graph softmax denominator -> final = 1/zsum
    softmax_final_kernel<<<G, HIDD>>>();

    // stage 7: out = final @ Wr + br
    readout_kernel<<<(G * 2 + 255) / 256, 256>>>(Wr, br, out, G);
}